// round 2
// baseline (speedup 1.0000x reference)
#include <cuda_runtime.h>
#include <math.h>

#define DD   1024
#define NH   16
#define HDIM 64
#define FF   2048
#define BB   8
#define SS   1027
#define EPSL 1e-5f

__device__ float g_seq[(size_t)BB * SS * DD];
__device__ float g_scores[(size_t)BB * SS * NH];
__device__ float g_q0[DD];
__device__ float g_qhat[NH * DD];
__device__ float g_qb[NH];
__device__ float g_ctxp[(size_t)BB * 8 * NH * DD];
__device__ float g_oattn[BB * DD];
__device__ float g_ores[BB * DD];
__device__ float g_h1[BB * DD];
__device__ float g_f[BB * FF];
__device__ float g_f2[BB * DD];

__global__ void k_gemv(const float* __restrict__ W, const float* __restrict__ xin,
                       const float* __restrict__ bias, const float* __restrict__ residE,
                       const float* __restrict__ residB, float* __restrict__ out,
                       int IN, int OUT, int doRelu) {
    int b    = blockIdx.y;
    int e    = blockIdx.x * 8 + (threadIdx.x >> 5);
    int lane = threadIdx.x & 31;
    if (e >= OUT) return;
    const float4* Wr = (const float4*)(W + (size_t)e * IN);
    const float4* xr = (const float4*)(xin + (size_t)b * IN);
    int n4 = IN >> 2;
    float acc = 0.f;
    for (int i = lane; i < n4; i += 32) {
        float4 w = Wr[i], x = xr[i];
        acc += w.x * x.x + w.y * x.y + w.z * x.z + w.w * x.w;
    }
    #pragma unroll
    for (int o = 16; o; o >>= 1) acc += __shfl_xor_sync(0xffffffffu, acc, o);
    if (lane == 0) {
        float v = acc;
        if (bias)   v += bias[e];
        if (residE) v += residE[e];
        if (residB) v += residB[(size_t)b * OUT + e];
        if (doRelu) v = fmaxf(v, 0.f);
        out[(size_t)b * OUT + e] = v;
    }
}

__global__ void k_qhat(const float* __restrict__ Wqkv, const float* __restrict__ bqkv) {
    int h = blockIdx.x >> 2;
    int q = blockIdx.x & 3;
    int t = threadIdx.x;
    __shared__ float q0s[HDIM];
    if (t < HDIM) q0s[t] = g_q0[h * HDIM + t];
    __syncthreads();
    int d = q * 256 + t;
    float acc = 0.f;
    #pragma unroll 4
    for (int j = 0; j < HDIM; j++)
        acc += q0s[j] * Wqkv[(size_t)(DD + h * HDIM + j) * DD + d];
    g_qhat[h * DD + d] = acc;
    if (q == 0 && t == 0) {
        float s = 0.f;
        for (int j = 0; j < HDIM; j++) s += q0s[j] * bqkv[DD + h * HDIM + j];
        g_qb[h] = s;
    }
}

#define TS 16
__global__ void k_merge_scores(const float* __restrict__ x, const float* __restrict__ y,
                               const float* __restrict__ cls, const float* __restrict__ sep,
                               const float* __restrict__ px, const float* __restrict__ py,
                               const int* __restrict__ x_len, const int* __restrict__ y_len) {
    int b  = blockIdx.y;
    int s0 = blockIdx.x * TS;
    int lx = x_len[b], ly = y_len[b];
    int Sb = lx + ly + 3;
    int t  = threadIdx.x;
    int w  = t >> 5, lane = t & 31;

    float qreg[32];
    #pragma unroll
    for (int k = 0; k < 32; k++) qreg[k] = g_qhat[w * DD + lane + 32 * k];
    float qb = g_qb[w];

    __shared__ __align__(16) float sh[DD];

    int sEnd = min(s0 + TS, Sb);
    for (int s = s0; s < sEnd; s++) {
        float v0, v1;
        if (s == 0)            { v0 = cls[t]; v1 = cls[t + 512]; }
        else if (s <= lx)      { const float* xr = x + ((size_t)b * 512 + (s - 1)) * DD;
                                 v0 = xr[t] + px[t]; v1 = xr[t + 512] + px[t + 512]; }
        else if (s == lx + 1)  { v0 = sep[t]; v1 = sep[t + 512]; }
        else if (s <= lx + ly + 1) { const float* yr = y + ((size_t)b * 512 + (s - lx - 2)) * DD;
                                 v0 = yr[t] + py[t]; v1 = yr[t + 512] + py[t + 512]; }
        else                   { v0 = sep[t]; v1 = sep[t + 512]; }
        float* sq = g_seq + ((size_t)b * SS + s) * DD;
        sq[t] = v0; sq[t + 512] = v1;
        sh[t] = v0; sh[t + 512] = v1;
        __syncthreads();
        float acc = 0.f;
        #pragma unroll
        for (int k = 0; k < 32; k++) acc += sh[lane + 32 * k] * qreg[k];
        #pragma unroll
        for (int o = 16; o; o >>= 1) acc += __shfl_xor_sync(0xffffffffu, acc, o);
        if (lane == 0)
            g_scores[((size_t)b * SS + s) * NH + w] = (acc + qb) * 0.125f;
        __syncthreads();
    }
}

__global__ void k_softmax(const int* __restrict__ x_len, const int* __restrict__ y_len) {
    int b = blockIdx.x;
    int w = threadIdx.x >> 5, lane = threadIdx.x & 31;
    int Sb = x_len[b] + y_len[b] + 3;
    float* sc = g_scores + (size_t)b * SS * NH;
    float m = -1e30f;
    for (int s = lane; s < Sb; s += 32) m = fmaxf(m, sc[s * NH + w]);
    #pragma unroll
    for (int o = 16; o; o >>= 1) m = fmaxf(m, __shfl_xor_sync(0xffffffffu, m, o));
    float sum = 0.f;
    for (int s = lane; s < Sb; s += 32) {
        float e = __expf(sc[s * NH + w] - m);
        sc[s * NH + w] = e;
        sum += e;
    }
    #pragma unroll
    for (int o = 16; o; o >>= 1) sum += __shfl_xor_sync(0xffffffffu, sum, o);
    float inv = 1.f / sum;
    for (int s = lane; s < Sb; s += 32) sc[s * NH + w] *= inv;
}

__global__ void k_ctx(const int* __restrict__ x_len, const int* __restrict__ y_len) {
    int c = blockIdx.x;
    int dh = blockIdx.y;
    int b = blockIdx.z;
    int Sb = x_len[b] + y_len[b] + 3;
    int cl = (Sb + 7) >> 3;
    int s0 = c * cl, s1 = min(s0 + cl, Sb);
    int d = dh * 512 + threadIdx.x;

    float acc[NH];
    #pragma unroll
    for (int h = 0; h < NH; h++) acc[h] = 0.f;

    const float* seqb = g_seq + (size_t)b * SS * DD;
    const float4* at  = (const float4*)(g_scores + (size_t)b * SS * NH);
    for (int s = s0; s < s1; s++) {
        float sv = seqb[(size_t)s * DD + d];
        float4 a0 = at[s * 4 + 0], a1 = at[s * 4 + 1], a2 = at[s * 4 + 2], a3 = at[s * 4 + 3];
        acc[0]  += a0.x * sv; acc[1]  += a0.y * sv; acc[2]  += a0.z * sv; acc[3]  += a0.w * sv;
        acc[4]  += a1.x * sv; acc[5]  += a1.y * sv; acc[6]  += a1.z * sv; acc[7]  += a1.w * sv;
        acc[8]  += a2.x * sv; acc[9]  += a2.y * sv; acc[10] += a2.z * sv; acc[11] += a2.w * sv;
        acc[12] += a3.x * sv; acc[13] += a3.y * sv; acc[14] += a3.z * sv; acc[15] += a3.w * sv;
    }
    float* outp = g_ctxp + (((size_t)b * 8 + c) * NH) * DD + d;
    #pragma unroll
    for (int h = 0; h < NH; h++) outp[(size_t)h * DD] = acc[h];
}

__global__ void k_oattn(const float* __restrict__ Wqkv, const float* __restrict__ bqkv) {
    int h = blockIdx.x, b = blockIdx.y;
    int t = threadIdx.x;
    __shared__ __align__(16) float ctx[DD];
    for (int d = t; d < DD; d += 256) {
        float s = 0.f;
        #pragma unroll
        for (int c = 0; c < 8; c++)
            s += g_ctxp[(((size_t)b * 8 + c) * NH + h) * DD + d];
        ctx[d] = s;
    }
    __syncthreads();
    int w = t >> 5, lane = t & 31;
    const float4* ctx4 = (const float4*)ctx;
    for (int jj = 0; jj < 8; jj++) {
        int e = h * HDIM + w * 8 + jj;
        const float4* Wr = (const float4*)(Wqkv + (size_t)(2 * DD + e) * DD);
        float acc = 0.f;
        for (int i = lane; i < DD / 4; i += 32) {
            float4 wv = Wr[i]; float4 cv = ctx4[i];
            acc += wv.x * cv.x + wv.y * cv.y + wv.z * cv.z + wv.w * cv.w;
        }
        #pragma unroll
        for (int o = 16; o; o >>= 1) acc += __shfl_xor_sync(0xffffffffu, acc, o);
        if (lane == 0) g_oattn[(size_t)b * DD + e] = acc + bqkv[2 * DD + e];
    }
}

__global__ void k_ln(const float* __restrict__ in, const float* __restrict__ gamma,
                     const float* __restrict__ beta, float* __restrict__ out) {
    int b = blockIdx.x, t = threadIdx.x;
    const float* row = in + (size_t)b * DD;
    __shared__ float sred[8];
    __shared__ float smv[2];

    float s = 0.f;
    for (int i = t; i < DD; i += 256) s += row[i];
    #pragma unroll
    for (int o = 16; o; o >>= 1) s += __shfl_xor_sync(0xffffffffu, s, o);
    if ((t & 31) == 0) sred[t >> 5] = s;
    __syncthreads();
    if (t == 0) {
        float m = 0.f;
        #pragma unroll
        for (int i = 0; i < 8; i++) m += sred[i];
        smv[0] = m * (1.f / DD);
    }
    __syncthreads();
    float m = smv[0];

    float v = 0.f;
    for (int i = t; i < DD; i += 256) { float dd = row[i] - m; v += dd * dd; }
    #pragma unroll
    for (int o = 16; o; o >>= 1) v += __shfl_xor_sync(0xffffffffu, v, o);
    __syncthreads();
    if ((t & 31) == 0) sred[t >> 5] = v;
    __syncthreads();
    if (t == 0) {
        float vv = 0.f;
        #pragma unroll
        for (int i = 0; i < 8; i++) vv += sred[i];
        smv[1] = rsqrtf(vv * (1.f / DD) + EPSL);
    }
    __syncthreads();
    float r = smv[1];
    for (int i = t; i < DD; i += 256)
        out[(size_t)b * DD + i] = (row[i] - m) * r * gamma[i] + beta[i];
}

extern "C" void kernel_launch(void* const* d_in, const int* in_sizes, int n_in,
                              void* d_out, int out_size) {
    const float* x     = (const float*)d_in[0];
    const float* y     = (const float*)d_in[1];
    const float* cls   = (const float*)d_in[2];
    const float* sep   = (const float*)d_in[3];
    const float* px    = (const float*)d_in[4];
    const float* py    = (const float*)d_in[5];
    const float* Wqkv  = (const float*)d_in[6];
    const float* bqkv  = (const float*)d_in[7];
    const float* Wo    = (const float*)d_in[8];
    const float* bo    = (const float*)d_in[9];
    const float* W1    = (const float*)d_in[10];
    const float* b1    = (const float*)d_in[11];
    const float* W2    = (const float*)d_in[12];
    const float* b2    = (const float*)d_in[13];
    const float* ln1g  = (const float*)d_in[14];
    const float* ln1b  = (const float*)d_in[15];
    const float* ln2g  = (const float*)d_in[16];
    const float* ln2b  = (const float*)d_in[17];
    const int*   x_len = (const int*)d_in[18];
    const int*   y_len = (const int*)d_in[19];
    float* outp = (float*)d_out;

    float *p_q0, *p_oattn, *p_ores, *p_h1, *p_f, *p_f2;
    cudaGetSymbolAddress((void**)&p_q0,    g_q0);
    cudaGetSymbolAddress((void**)&p_oattn, g_oattn);
    cudaGetSymbolAddress((void**)&p_ores,  g_ores);
    cudaGetSymbolAddress((void**)&p_h1,    g_h1);
    cudaGetSymbolAddress((void**)&p_f,     g_f);
    cudaGetSymbolAddress((void**)&p_f2,    g_f2);

    k_gemv<<<dim3(128, 1), 256>>>(Wqkv, cls, bqkv, nullptr, nullptr, p_q0, DD, DD, 0);
    k_qhat<<<64, 256>>>(Wqkv, bqkv);
    k_merge_scores<<<dim3((SS + TS - 1) / TS, BB), 512>>>(x, y, cls, sep, px, py, x_len, y_len);
    k_softmax<<<BB, 512>>>(x_len, y_len);
    k_ctx<<<dim3(8, 2, BB), 512>>>(x_len, y_len);
    k_oattn<<<dim3(NH, BB), 256>>>(Wqkv, bqkv);
    k_gemv<<<dim3(128, BB), 256>>>(Wo, p_oattn, bo, cls, nullptr, p_ores, DD, DD, 0);
    k_ln<<<BB, 256>>>(p_ores, ln1g, ln1b, p_h1);
    k_gemv<<<dim3(256, BB), 256>>>(W1, p_h1, b1, nullptr, nullptr, p_f, DD, FF, 1);
    k_gemv<<<dim3(128, BB), 256>>>(W2, p_f, b2, nullptr, p_h1, p_f2, FF, DD, 0);
    k_ln<<<BB, 256>>>(p_f2, ln2g, ln2b, outp);
}

// round 4
// speedup vs baseline: 1.0303x; 1.0303x over previous
#include <cuda_runtime.h>
#include <math.h>

#define DD   1024
#define NH   16
#define HDIM 64
#define FF   2048
#define BB   8
#define SS   1027
#define SP   1056            // padded score stride per (b,h)
#define EPSL 1e-5f

__device__ float g_seq[(size_t)BB * SS * DD];
__device__ float g_scores[(size_t)BB * NH * SP];     // [b][h][s]
__device__ float g_minv[BB * NH * 2];                // (max, 1/sum)
__device__ float g_qhat[NH * DD];
__device__ float g_qb[NH];
__device__ float g_ctxp[(size_t)BB * 8 * NH * DD];   // split-s partial ctx
__device__ float g_ctx[(size_t)BB * NH * DD];        // reduced ctx per head
__device__ float g_oattn[BB * DD];
__device__ float g_ores[BB * DD];
__device__ float g_h1[BB * DD];
__device__ float g_f[BB * FF];
__device__ float g_f2[BB * DD];

// ---------- fused q0 + qhat: one block per head -----------------------------
__global__ void k_q0qhat(const float* __restrict__ Wqkv, const float* __restrict__ bqkv,
                         const float* __restrict__ cls) {
    int h = blockIdx.x;
    int t = threadIdx.x;                 // 256
    int w = t >> 5, lane = t & 31;
    __shared__ __align__(16) float clss[DD];
    __shared__ float q0s[HDIM];

    for (int i = t; i < DD / 4; i += 256)
        ((float4*)clss)[i] = ((const float4*)cls)[i];
    __syncthreads();

    // phase 1: q0s[j] = Wq[h*64+j] . cls + bq   (8 warps x 8 rows)
    const float4* c4 = (const float4*)clss;
    for (int jr = 0; jr < 8; jr++) {
        int j = w * 8 + jr;
        const float4* Wr = (const float4*)(Wqkv + (size_t)(h * HDIM + j) * DD);
        float acc = 0.f;
        for (int i = lane; i < DD / 4; i += 32) {
            float4 wv = Wr[i], cv = c4[i];
            acc += wv.x * cv.x + wv.y * cv.y + wv.z * cv.z + wv.w * cv.w;
        }
        #pragma unroll
        for (int o = 16; o; o >>= 1) acc += __shfl_xor_sync(0xffffffffu, acc, o);
        if (lane == 0) q0s[j] = acc + bqkv[h * HDIM + j];
    }
    __syncthreads();

    // phase 2: qhat[h][d] = sum_j q0s[j] * Wk[h*64+j][d]
    #pragma unroll
    for (int g = 0; g < 4; g++) {
        int d = g * 256 + t;
        float acc = 0.f;
        #pragma unroll 4
        for (int j = 0; j < HDIM; j++)
            acc += q0s[j] * Wqkv[(size_t)(DD + h * HDIM + j) * DD + d];
        g_qhat[h * DD + d] = acc;
    }
    if (t == 0) {
        float s = 0.f;
        for (int j = 0; j < HDIM; j++) s += q0s[j] * bqkv[DD + h * HDIM + j];
        g_qb[h] = s;
    }
}

// ---------- merge + scores (double-buffered smem) ---------------------------
#define TS 16
__global__ void k_merge_scores(const float* __restrict__ x, const float* __restrict__ y,
                               const float* __restrict__ cls, const float* __restrict__ sep,
                               const float* __restrict__ px, const float* __restrict__ py,
                               const int* __restrict__ x_len, const int* __restrict__ y_len) {
    int b  = blockIdx.y;
    int s0 = blockIdx.x * TS;
    int lx = x_len[b], ly = y_len[b];
    int Sb = lx + ly + 3;
    if (s0 >= Sb) return;
    int t  = threadIdx.x;
    int w  = t >> 5, lane = t & 31;

    float qreg[32];
    #pragma unroll
    for (int k = 0; k < 32; k++) qreg[k] = g_qhat[w * DD + lane + 32 * k];
    float qb = g_qb[w];

    __shared__ __align__(16) float sh[2][DD];

    int sEnd = min(s0 + TS, Sb);
    int p = 0;
    for (int s = s0; s < sEnd; s++, p ^= 1) {
        float v0, v1;
        if (s == 0)            { v0 = cls[t]; v1 = cls[t + 512]; }
        else if (s <= lx)      { const float* xr = x + ((size_t)b * 512 + (s - 1)) * DD;
                                 v0 = xr[t] + px[t]; v1 = xr[t + 512] + px[t + 512]; }
        else if (s == lx + 1)  { v0 = sep[t]; v1 = sep[t + 512]; }
        else if (s <= lx + ly + 1) { const float* yr = y + ((size_t)b * 512 + (s - lx - 2)) * DD;
                                 v0 = yr[t] + py[t]; v1 = yr[t + 512] + py[t + 512]; }
        else                   { v0 = sep[t]; v1 = sep[t + 512]; }
        float* sq = g_seq + ((size_t)b * SS + s) * DD;
        sq[t] = v0; sq[t + 512] = v1;
        sh[p][t] = v0; sh[p][t + 512] = v1;
        __syncthreads();
        float acc = 0.f;
        #pragma unroll
        for (int k = 0; k < 32; k++) acc += sh[p][lane + 32 * k] * qreg[k];
        #pragma unroll
        for (int o = 16; o; o >>= 1) acc += __shfl_xor_sync(0xffffffffu, acc, o);
        if (lane == 0)
            g_scores[((size_t)b * NH + w) * SP + s] = (acc + qb) * 0.125f;
    }
}

// ---------- softmax stats: block per (b,h) over contiguous scores -----------
__global__ void k_stats(const int* __restrict__ x_len, const int* __restrict__ y_len) {
    int bh = blockIdx.x;
    int b  = bh >> 4;
    int Sb = x_len[b] + y_len[b] + 3;
    int t  = threadIdx.x;                // 256
    const float* sc = g_scores + (size_t)bh * SP;
    __shared__ float sred[8];

    float m = -1e30f;
    for (int s = t; s < Sb; s += 256) m = fmaxf(m, sc[s]);
    #pragma unroll
    for (int o = 16; o; o >>= 1) m = fmaxf(m, __shfl_xor_sync(0xffffffffu, m, o));
    if ((t & 31) == 0) sred[t >> 5] = m;
    __syncthreads();
    m = sred[0];
    #pragma unroll
    for (int i = 1; i < 8; i++) m = fmaxf(m, sred[i]);

    float sum = 0.f;
    for (int s = t; s < Sb; s += 256) sum += __expf(sc[s] - m);
    #pragma unroll
    for (int o = 16; o; o >>= 1) sum += __shfl_xor_sync(0xffffffffu, sum, o);
    __syncthreads();
    if ((t & 31) == 0) sred[t >> 5] = sum;
    __syncthreads();
    if (t == 0) {
        float ss = 0.f;
        #pragma unroll
        for (int i = 0; i < 8; i++) ss += sred[i];
        g_minv[bh * 2]     = m;
        g_minv[bh * 2 + 1] = 1.f / ss;
    }
}

// ---------- ctx partials with fused softmax normalize -----------------------
__global__ void k_ctx(const int* __restrict__ x_len, const int* __restrict__ y_len) {
    int c  = blockIdx.x;           // 0..7
    int dh = blockIdx.y;           // 0..1
    int b  = blockIdx.z;
    int Sb = x_len[b] + y_len[b] + 3;
    int cl = (Sb + 7) >> 3;
    int s0 = c * cl, s1 = min(s0 + cl, Sb);
    int n  = s1 - s0;
    int t  = threadIdx.x;          // 512
    int d  = dh * 512 + t;

    __shared__ float a[NH][132];   // normalized attn chunk (cl <= 129)
    __shared__ float minv[NH][2];
    if (t < NH * 2) ((float*)minv)[t] = g_minv[(b * NH) * 2 + t];
    __syncthreads();
    for (int i = t; i < n * NH; i += 512) {
        int h = i & 15, ss = i >> 4;
        a[h][ss] = __expf(g_scores[((size_t)b * NH + h) * SP + s0 + ss] - minv[h][0]) * minv[h][1];
    }
    __syncthreads();

    float acc[NH];
    #pragma unroll
    for (int h = 0; h < NH; h++) acc[h] = 0.f;
    const float* seqb = g_seq + (size_t)b * SS * DD;
    for (int ss = 0; ss < n; ss++) {
        float sv = seqb[(size_t)(s0 + ss) * DD + d];
        #pragma unroll
        for (int h = 0; h < NH; h++) acc[h] += a[h][ss] * sv;
    }
    float* outp = g_ctxp + (((size_t)b * 8 + c) * NH) * DD + d;
    #pragma unroll
    for (int h = 0; h < NH; h++) outp[(size_t)h * DD] = acc[h];
}

// ---------- reduce ctx chunks (FIXED: cover all NH*DD = 16384 per batch) -----
__global__ void k_ctxreduce() {
    int b = blockIdx.x;
    int q = blockIdx.y;            // 0..3
    int t = threadIdx.x;           // 512
    #pragma unroll
    for (int k = 0; k < 8; k++) {
        int idx = q * 4096 + k * 512 + t;      // over NH*DD = 16384
        float s = 0.f;
        #pragma unroll
        for (int c = 0; c < 8; c++)
            s += g_ctxp[((size_t)b * 8 + c) * (NH * DD) + idx];
        g_ctx[(size_t)b * (NH * DD) + idx] = s;
    }
}

// ---------- V projection: batch-shared, per-head ctx -------------------------
__global__ void k_gemvV(const float* __restrict__ Wqkv, const float* __restrict__ bqkv) {
    __shared__ __align__(16) float xs[BB * DD];    // 32KB
    int t = threadIdx.x;           // 256
    int w = t >> 5, lane = t & 31;
    int e0 = blockIdx.x * 16;
    int h  = e0 >> 6;

    float4* xs4 = (float4*)xs;
    for (int i = t; i < BB * DD / 4; i += 256) {
        int b = i >> 8, j4 = i & 255;
        xs4[i] = ((const float4*)(g_ctx + ((size_t)b * NH + h) * DD))[j4];
    }
    __syncthreads();

    int e = e0 + w * 2;
    const float4* W0 = (const float4*)(Wqkv + (size_t)(2 * DD + e) * DD);
    const float4* W1r = (const float4*)(Wqkv + (size_t)(2 * DD + e + 1) * DD);
    float acc[2][BB];
    #pragma unroll
    for (int r = 0; r < 2; r++)
        #pragma unroll
        for (int b = 0; b < BB; b++) acc[r][b] = 0.f;

    for (int i = lane; i < DD / 4; i += 32) {
        float4 w0 = W0[i], w1 = W1r[i];
        #pragma unroll
        for (int b = 0; b < BB; b++) {
            float4 x4 = xs4[b * 256 + i];
            acc[0][b] += w0.x * x4.x + w0.y * x4.y + w0.z * x4.z + w0.w * x4.w;
            acc[1][b] += w1.x * x4.x + w1.y * x4.y + w1.z * x4.z + w1.w * x4.w;
        }
    }
    #pragma unroll
    for (int r = 0; r < 2; r++)
        #pragma unroll
        for (int b = 0; b < BB; b++) {
            #pragma unroll
            for (int o = 16; o; o >>= 1)
                acc[r][b] += __shfl_xor_sync(0xffffffffu, acc[r][b], o);
        }
    if (lane == 0) {
        #pragma unroll
        for (int r = 0; r < 2; r++) {
            float be = bqkv[2 * DD + e + r];
            #pragma unroll
            for (int b = 0; b < BB; b++)
                g_oattn[(size_t)b * DD + e + r] = acc[r][b] + be;
        }
    }
}

// ---------- batch-shared GEMV: out[b,e] = W[e].x[b] + bias + residE + residB -
__global__ void k_gemv8(const float* __restrict__ W, const float* __restrict__ xin,
                        const float* __restrict__ bias, const float* __restrict__ residE,
                        const float* __restrict__ residB, float* __restrict__ out,
                        int IN, int OUT, int doRelu) {
    __shared__ __align__(16) float xs[BB * 1024];  // 32KB
    int t = threadIdx.x;           // 256
    int w = t >> 5, lane = t & 31;
    int e = blockIdx.x * 16 + w * 2;

    float acc[2][BB];
    #pragma unroll
    for (int r = 0; r < 2; r++)
        #pragma unroll
        for (int b = 0; b < BB; b++) acc[r][b] = 0.f;

    float4* xs4 = (float4*)xs;
    int nchunk = IN >> 10;
    for (int kc = 0; kc < nchunk; kc++) {
        for (int i = t; i < BB * 256; i += 256) {
            int b = i >> 8, j4 = i & 255;
            xs4[i] = ((const float4*)(xin + (size_t)b * IN + kc * 1024))[j4];
        }
        __syncthreads();
        const float4* W0 = (const float4*)(W + (size_t)e * IN + kc * 1024);
        const float4* W1r = (const float4*)(W + (size_t)(e + 1) * IN + kc * 1024);
        for (int i = lane; i < 256; i += 32) {
            float4 w0 = W0[i], w1 = W1r[i];
            #pragma unroll
            for (int b = 0; b < BB; b++) {
                float4 x4 = xs4[b * 256 + i];
                acc[0][b] += w0.x * x4.x + w0.y * x4.y + w0.z * x4.z + w0.w * x4.w;
                acc[1][b] += w1.x * x4.x + w1.y * x4.y + w1.z * x4.z + w1.w * x4.w;
            }
        }
        __syncthreads();
    }
    #pragma unroll
    for (int r = 0; r < 2; r++)
        #pragma unroll
        for (int b = 0; b < BB; b++) {
            #pragma unroll
            for (int o = 16; o; o >>= 1)
                acc[r][b] += __shfl_xor_sync(0xffffffffu, acc[r][b], o);
        }
    if (lane == 0) {
        #pragma unroll
        for (int r = 0; r < 2; r++) {
            int ee = e + r;
            float be = (bias ? bias[ee] : 0.f) + (residE ? residE[ee] : 0.f);
            #pragma unroll
            for (int b = 0; b < BB; b++) {
                float v = acc[r][b] + be;
                if (residB) v += residB[(size_t)b * OUT + ee];
                if (doRelu) v = fmaxf(v, 0.f);
                out[(size_t)b * OUT + ee] = v;
            }
        }
    }
}

// ---------- LayerNorm --------------------------------------------------------
__global__ void k_ln(const float* __restrict__ in, const float* __restrict__ gamma,
                     const float* __restrict__ beta, float* __restrict__ out) {
    int b = blockIdx.x, t = threadIdx.x;  // 256
    const float* row = in + (size_t)b * DD;
    __shared__ float sred[8];
    __shared__ float smv[2];

    float s = 0.f;
    for (int i = t; i < DD; i += 256) s += row[i];
    #pragma unroll
    for (int o = 16; o; o >>= 1) s += __shfl_xor_sync(0xffffffffu, s, o);
    if ((t & 31) == 0) sred[t >> 5] = s;
    __syncthreads();
    if (t == 0) {
        float m = 0.f;
        #pragma unroll
        for (int i = 0; i < 8; i++) m += sred[i];
        smv[0] = m * (1.f / DD);
    }
    __syncthreads();
    float m = smv[0];

    float v = 0.f;
    for (int i = t; i < DD; i += 256) { float dd2 = row[i] - m; v += dd2 * dd2; }
    #pragma unroll
    for (int o = 16; o; o >>= 1) v += __shfl_xor_sync(0xffffffffu, v, o);
    __syncthreads();
    if ((t & 31) == 0) sred[t >> 5] = v;
    __syncthreads();
    if (t == 0) {
        float vv = 0.f;
        #pragma unroll
        for (int i = 0; i < 8; i++) vv += sred[i];
        smv[1] = rsqrtf(vv * (1.f / DD) + EPSL);
    }
    __syncthreads();
    float r = smv[1];
    for (int i = t; i < DD; i += 256)
        out[(size_t)b * DD + i] = (row[i] - m) * r * gamma[i] + beta[i];
}

extern "C" void kernel_launch(void* const* d_in, const int* in_sizes, int n_in,
                              void* d_out, int out_size) {
    const float* x     = (const float*)d_in[0];
    const float* y     = (const float*)d_in[1];
    const float* cls   = (const float*)d_in[2];
    const float* sep   = (const float*)d_in[3];
    const float* px    = (const float*)d_in[4];
    const float* py    = (const float*)d_in[5];
    const float* Wqkv  = (const float*)d_in[6];
    const float* bqkv  = (const float*)d_in[7];
    const float* Wo    = (const float*)d_in[8];
    const float* bo    = (const float*)d_in[9];
    const float* W1    = (const float*)d_in[10];
    const float* b1    = (const float*)d_in[11];
    const float* W2    = (const float*)d_in[12];
    const float* b2    = (const float*)d_in[13];
    const float* ln1g  = (const float*)d_in[14];
    const float* ln1b  = (const float*)d_in[15];
    const float* ln2g  = (const float*)d_in[16];
    const float* ln2b  = (const float*)d_in[17];
    const int*   x_len = (const int*)d_in[18];
    const int*   y_len = (const int*)d_in[19];
    float* outp = (float*)d_out;

    float *p_oattn, *p_ores, *p_h1, *p_f, *p_f2;
    cudaGetSymbolAddress((void**)&p_oattn, g_oattn);
    cudaGetSymbolAddress((void**)&p_ores,  g_ores);
    cudaGetSymbolAddress((void**)&p_h1,    g_h1);
    cudaGetSymbolAddress((void**)&p_f,     g_f);
    cudaGetSymbolAddress((void**)&p_f2,    g_f2);

    k_q0qhat<<<NH, 256>>>(Wqkv, bqkv, cls);
    k_merge_scores<<<dim3((SS + TS - 1) / TS, BB), 512>>>(x, y, cls, sep, px, py, x_len, y_len);
    k_stats<<<BB * NH, 256>>>(x_len, y_len);
    k_ctx<<<dim3(8, 2, BB), 512>>>(x_len, y_len);
    k_ctxreduce<<<dim3(BB, 4), 512>>>();
    k_gemvV<<<DD / 16, 256>>>(Wqkv, bqkv);
    k_gemv8<<<DD / 16, 256>>>(Wo, p_oattn, bo, cls, nullptr, p_ores, DD, DD, 0);
    k_ln<<<BB, 256>>>(p_ores, ln1g, ln1b, p_h1);
    k_gemv8<<<FF / 16, 256>>>(W1, p_h1, b1, nullptr, nullptr, p_f, DD, FF, 1);
    k_gemv8<<<DD / 16, 256>>>(W2, p_f, b2, nullptr, p_h1, p_f2, FF, DD, 0);
    k_ln<<<BB, 256>>>(p_f2, ln2g, ln2b, outp);
}

// round 5
// speedup vs baseline: 1.3716x; 1.3312x over previous
#include <cuda_runtime.h>
#include <math.h>

#define DD   1024
#define NH   16
#define HDIM 64
#define FF   2048
#define BB   8
#define SS   1027
#define SP   1056
#define EPSL 1e-5f
#define NC   8              // s-chunks for ctx

__device__ float g_scores[(size_t)BB * NH * SP];     // [b][h][s]
__device__ float g_minv[BB * NH * 2];                // (max, 1/sum)
__device__ float g_qhat[NH * DD];
__device__ float g_qb[NH];
__device__ float g_ctxp[(size_t)BB * NC * NH * DD];  // split-s partial ctx
__device__ float g_ctx[(size_t)BB * NH * DD];
__device__ float g_oattn[BB * DD];
__device__ float g_ores[BB * DD];
__device__ float g_h1[BB * DD];
__device__ float g_f[BB * FF];
__device__ float g_f2[BB * DD];

// ---------- q0 + qhat: grid (NH, 4), phase1 redundant per quarter ------------
__global__ void k_q0qhat(const float* __restrict__ Wqkv, const float* __restrict__ bqkv,
                         const float* __restrict__ cls) {
    int h = blockIdx.x, q = blockIdx.y;
    int t = threadIdx.x;                 // 256
    int w = t >> 5, lane = t & 31;
    __shared__ __align__(16) float clss[DD];
    __shared__ float q0s[HDIM];

    for (int i = t; i < DD / 4; i += 256)
        ((float4*)clss)[i] = ((const float4*)cls)[i];
    __syncthreads();

    const float4* c4 = (const float4*)clss;
    for (int jr = 0; jr < 8; jr++) {
        int j = w * 8 + jr;
        const float4* Wr = (const float4*)(Wqkv + (size_t)(h * HDIM + j) * DD);
        float acc = 0.f;
        for (int i = lane; i < DD / 4; i += 32) {
            float4 wv = Wr[i], cv = c4[i];
            acc += wv.x * cv.x + wv.y * cv.y + wv.z * cv.z + wv.w * cv.w;
        }
        #pragma unroll
        for (int o = 16; o; o >>= 1) acc += __shfl_xor_sync(0xffffffffu, acc, o);
        if (lane == 0) q0s[j] = acc + bqkv[h * HDIM + j];
    }
    __syncthreads();

    int d = q * 256 + t;
    float acc = 0.f;
    #pragma unroll 4
    for (int j = 0; j < HDIM; j++)
        acc += q0s[j] * Wqkv[(size_t)(DD + h * HDIM + j) * DD + d];
    g_qhat[h * DD + d] = acc;
    if (q == 0 && t == 0) {
        float s = 0.f;
        for (int j = 0; j < HDIM; j++) s += q0s[j] * bqkv[DD + h * HDIM + j];
        g_qb[h] = s;
    }
}

// ---------- scores: warp per position, qhat in dynamic smem ------------------
// grid (16, BB), block 256 (8 warps). dsm = qhat(16K) + px(1K) + py(1K) + qb(16)
__global__ void k_scores(const float* __restrict__ x, const float* __restrict__ y,
                         const float* __restrict__ cls, const float* __restrict__ sep,
                         const float* __restrict__ px, const float* __restrict__ py,
                         const int* __restrict__ x_len, const int* __restrict__ y_len) {
    extern __shared__ __align__(16) float dsm[];
    float* qh  = dsm;                    // 16384
    float* pxs = dsm + NH * DD;          // 1024
    float* pys = pxs + DD;               // 1024
    float* qbs = pys + DD;               // 16
    int b = blockIdx.y;
    int t = threadIdx.x, w = t >> 5, lane = t & 31;

    float4* qh4 = (float4*)qh;
    for (int i = t; i < NH * DD / 4; i += 256) qh4[i] = ((const float4*)g_qhat)[i];
    if (t < 256) { ((float4*)pxs)[t] = ((const float4*)px)[t]; ((float4*)pys)[t] = ((const float4*)py)[t]; }
    if (t < NH) qbs[t] = g_qb[t];
    __syncthreads();

    int lx = x_len[b], ly = y_len[b];
    int Sb = lx + ly + 3;
    const float4* pxs4 = (const float4*)pxs;
    const float4* pys4 = (const float4*)pys;

    for (int s = blockIdx.x * 8 + w; s < Sb; s += 128) {
        float4 v[8];
        if (s == 0) {
            const float4* c4 = (const float4*)cls;
            #pragma unroll
            for (int k = 0; k < 8; k++) v[k] = __ldg(&c4[lane + 32 * k]);
        } else if (s <= lx) {
            const float4* xr = (const float4*)(x + ((size_t)b * 512 + (s - 1)) * DD);
            #pragma unroll
            for (int k = 0; k < 8; k++) {
                float4 a = __ldg(&xr[lane + 32 * k]), p = pxs4[lane + 32 * k];
                v[k].x = a.x + p.x; v[k].y = a.y + p.y; v[k].z = a.z + p.z; v[k].w = a.w + p.w;
            }
        } else if (s == lx + 1 || s == lx + ly + 2) {
            const float4* s4 = (const float4*)sep;
            #pragma unroll
            for (int k = 0; k < 8; k++) v[k] = __ldg(&s4[lane + 32 * k]);
        } else {
            const float4* yr = (const float4*)(y + ((size_t)b * 512 + (s - lx - 2)) * DD);
            #pragma unroll
            for (int k = 0; k < 8; k++) {
                float4 a = __ldg(&yr[lane + 32 * k]), p = pys4[lane + 32 * k];
                v[k].x = a.x + p.x; v[k].y = a.y + p.y; v[k].z = a.z + p.z; v[k].w = a.w + p.w;
            }
        }
        float acc[NH];
        #pragma unroll
        for (int h = 0; h < NH; h++) {
            float a = 0.f;
            const float4* q4 = qh4 + h * 256;
            #pragma unroll
            for (int k = 0; k < 8; k++) {
                float4 qv = q4[lane + 32 * k];
                a += qv.x * v[k].x + qv.y * v[k].y + qv.z * v[k].z + qv.w * v[k].w;
            }
            acc[h] = a;
        }
        #pragma unroll
        for (int h = 0; h < NH; h++) {
            #pragma unroll
            for (int o = 16; o; o >>= 1)
                acc[h] += __shfl_xor_sync(0xffffffffu, acc[h], o);
        }
        if (lane == 0) {
            #pragma unroll
            for (int h = 0; h < NH; h++)
                g_scores[((size_t)b * NH + h) * SP + s] = (acc[h] + qbs[h]) * 0.125f;
        }
    }
}

// ---------- softmax stats ----------------------------------------------------
__global__ void k_stats(const int* __restrict__ x_len, const int* __restrict__ y_len) {
    int bh = blockIdx.x;
    int b  = bh >> 4;
    int Sb = x_len[b] + y_len[b] + 3;
    int t  = threadIdx.x;                // 256
    const float* sc = g_scores + (size_t)bh * SP;
    __shared__ float sred[8];

    float m = -1e30f;
    for (int s = t; s < Sb; s += 256) m = fmaxf(m, sc[s]);
    #pragma unroll
    for (int o = 16; o; o >>= 1) m = fmaxf(m, __shfl_xor_sync(0xffffffffu, m, o));
    if ((t & 31) == 0) sred[t >> 5] = m;
    __syncthreads();
    m = sred[0];
    #pragma unroll
    for (int i = 1; i < 8; i++) m = fmaxf(m, sred[i]);

    float sum = 0.f;
    for (int s = t; s < Sb; s += 256) sum += __expf(sc[s] - m);
    #pragma unroll
    for (int o = 16; o; o >>= 1) sum += __shfl_xor_sync(0xffffffffu, sum, o);
    __syncthreads();
    if ((t & 31) == 0) sred[t >> 5] = sum;
    __syncthreads();
    if (t == 0) {
        float ss = 0.f;
        #pragma unroll
        for (int i = 0; i < 8; i++) ss += sred[i];
        g_minv[bh * 2]     = m;
        g_minv[bh * 2 + 1] = 1.f / ss;
    }
}

// ---------- ctx partials: recompute merge, contiguous sub-loops --------------
// grid (NC, 8 d-slices, BB), block 128. d = dq*128 + t.
__global__ void k_ctx(const float* __restrict__ x, const float* __restrict__ y,
                      const float* __restrict__ cls, const float* __restrict__ sep,
                      const float* __restrict__ px, const float* __restrict__ py,
                      const int* __restrict__ x_len, const int* __restrict__ y_len) {
    int c  = blockIdx.x;
    int dq = blockIdx.y;
    int b  = blockIdx.z;
    int t  = threadIdx.x;          // 128
    int d  = dq * 128 + t;
    int lx = x_len[b], ly = y_len[b];
    int Sb = lx + ly + 3;
    int cl = (Sb + NC - 1) / NC;
    int s0 = c * cl, s1 = min(s0 + cl, Sb);
    int n  = s1 - s0;

    float* outp = g_ctxp + (((size_t)b * NC + c) * NH) * DD + d;
    if (n <= 0) {
        #pragma unroll
        for (int h = 0; h < NH; h++) outp[(size_t)h * DD] = 0.f;
        return;
    }

    __shared__ float a[NH][132];
    __shared__ float minv[NH * 2];
    if (t < NH * 2) minv[t] = g_minv[b * NH * 2 + t];
    __syncthreads();
    for (int i = t; i < n * NH; i += 128) {
        int h = i & 15, ss = i >> 4;
        a[h][ss] = __expf(g_scores[((size_t)b * NH + h) * SP + s0 + ss] - minv[h * 2]) * minv[h * 2 + 1];
    }
    __syncthreads();

    float acc[NH];
    #pragma unroll
    for (int h = 0; h < NH; h++) acc[h] = 0.f;

    // cls at s = 0
    if (s0 == 0) {
        float v = cls[d];
        #pragma unroll
        for (int h = 0; h < NH; h++) acc[h] += a[h][0] * v;
    }
    // x run: s in [1, lx]
    {
        int p0 = max(s0, 1), p1 = min(s1, lx + 1);
        float pxd = px[d];
        const float* xp = x + (size_t)b * 512 * DD + d;
        #pragma unroll 4
        for (int s = p0; s < p1; s++) {
            float v = xp[(size_t)(s - 1) * DD] + pxd;
            int ss = s - s0;
            #pragma unroll
            for (int h = 0; h < NH; h++) acc[h] += a[h][ss] * v;
        }
    }
    // sep1 / sep2
    {
        float sd = sep[d];
        int sA = lx + 1, sB = lx + ly + 2;
        if (sA >= s0 && sA < s1) {
            #pragma unroll
            for (int h = 0; h < NH; h++) acc[h] += a[h][sA - s0] * sd;
        }
        if (sB >= s0 && sB < s1) {
            #pragma unroll
            for (int h = 0; h < NH; h++) acc[h] += a[h][sB - s0] * sd;
        }
    }
    // y run: s in [lx+2, lx+ly+1]
    {
        int p0 = max(s0, lx + 2), p1 = min(s1, lx + ly + 2);
        float pyd = py[d];
        const float* yp = y + (size_t)b * 512 * DD + d;
        #pragma unroll 4
        for (int s = p0; s < p1; s++) {
            float v = yp[(size_t)(s - lx - 2) * DD] + pyd;
            int ss = s - s0;
            #pragma unroll
            for (int h = 0; h < NH; h++) acc[h] += a[h][ss] * v;
        }
    }
    #pragma unroll
    for (int h = 0; h < NH; h++) outp[(size_t)h * DD] = acc[h];
}

// ---------- reduce ctx chunks -------------------------------------------------
__global__ void k_ctxreduce() {
    int b = blockIdx.x;
    int q = blockIdx.y;            // 0..3
    int t = threadIdx.x;           // 512
    #pragma unroll
    for (int k = 0; k < 8; k++) {
        int idx = q * 4096 + k * 512 + t;
        float s = 0.f;
        #pragma unroll
        for (int c = 0; c < NC; c++)
            s += g_ctxp[((size_t)b * NC + c) * (NH * DD) + idx];
        g_ctx[(size_t)b * (NH * DD) + idx] = s;
    }
}

// ---------- V projection: 1 row/warp, per-head ctx ----------------------------
__global__ void k_gemvV(const float* __restrict__ Wqkv, const float* __restrict__ bqkv) {
    __shared__ __align__(16) float xs[BB * DD];
    int t = threadIdx.x;           // 256
    int w = t >> 5, lane = t & 31;
    int e = blockIdx.x * 8 + w;
    int h = (blockIdx.x * 8) >> 6;

    float4* xs4 = (float4*)xs;
    for (int i = t; i < BB * DD / 4; i += 256) {
        int b = i >> 8, j4 = i & 255;
        xs4[i] = ((const float4*)(g_ctx + ((size_t)b * NH + h) * DD))[j4];
    }
    __syncthreads();

    const float4* Wr = (const float4*)(Wqkv + (size_t)(2 * DD + e) * DD);
    float acc[BB];
    #pragma unroll
    for (int b = 0; b < BB; b++) acc[b] = 0.f;
    for (int i = lane; i < DD / 4; i += 32) {
        float4 wv = Wr[i];
        #pragma unroll
        for (int b = 0; b < BB; b++) {
            float4 x4 = xs4[b * 256 + i];
            acc[b] += wv.x * x4.x + wv.y * x4.y + wv.z * x4.z + wv.w * x4.w;
        }
    }
    #pragma unroll
    for (int b = 0; b < BB; b++) {
        #pragma unroll
        for (int o = 16; o; o >>= 1)
            acc[b] += __shfl_xor_sync(0xffffffffu, acc[b], o);
    }
    if (lane == 0) {
        float be = bqkv[2 * DD + e];
        #pragma unroll
        for (int b = 0; b < BB; b++)
            g_oattn[(size_t)b * DD + e] = acc[b] + be;
    }
}

// ---------- batch-shared GEMV, optional fused input-LN ------------------------
// 1 row/warp, grid = OUT/8, block 256.
__global__ void k_gemv8(const float* __restrict__ W, const float* __restrict__ xin,
                        const float* __restrict__ bias, const float* __restrict__ residE,
                        const float* __restrict__ residB, float* __restrict__ out,
                        int IN, int OUT, int doRelu,
                        int doLN, const float* __restrict__ lng, const float* __restrict__ lnb,
                        float* __restrict__ h1out) {
    __shared__ __align__(16) float xs[BB * 1024];
    __shared__ __align__(16) float gs[1024], bs[1024];
    int t = threadIdx.x;           // 256
    int w = t >> 5, lane = t & 31;
    int e = blockIdx.x * 8 + w;

    float acc[BB];
    #pragma unroll
    for (int b = 0; b < BB; b++) acc[b] = 0.f;

    float4* xs4 = (float4*)xs;
    int nchunk = IN >> 10;
    for (int kc = 0; kc < nchunk; kc++) {
        for (int i = t; i < BB * 256; i += 256) {
            int b = i >> 8, j4 = i & 255;
            xs4[i] = ((const float4*)(xin + (size_t)b * IN + kc * 1024))[j4];
        }
        if (doLN) {
            if (t < 256) { ((float4*)gs)[t] = ((const float4*)lng)[t]; ((float4*)bs)[t] = ((const float4*)lnb)[t]; }
            __syncthreads();
            // warp w normalizes batch w's row in place
            float* row = xs + w * 1024;
            float s = 0.f;
            #pragma unroll
            for (int j = 0; j < 32; j++) s += row[lane + 32 * j];
            #pragma unroll
            for (int o = 16; o; o >>= 1) s += __shfl_xor_sync(0xffffffffu, s, o);
            float m = s * (1.f / 1024.f);
            float v = 0.f;
            #pragma unroll
            for (int j = 0; j < 32; j++) { float dd2 = row[lane + 32 * j] - m; v += dd2 * dd2; }
            #pragma unroll
            for (int o = 16; o; o >>= 1) v += __shfl_xor_sync(0xffffffffu, v, o);
            float r = rsqrtf(v * (1.f / 1024.f) + EPSL);
            #pragma unroll
            for (int j = 0; j < 32; j++) {
                int idx = lane + 32 * j;
                row[idx] = (row[idx] - m) * r * gs[idx] + bs[idx];
            }
            __syncthreads();
            if (h1out && blockIdx.x == 0) {
                for (int i = t; i < BB * 256; i += 256)
                    ((float4*)h1out)[i] = xs4[i];
            }
        } else {
            __syncthreads();
        }
        const float4* Wr = (const float4*)(W + (size_t)e * IN + kc * 1024);
        for (int i = lane; i < 256; i += 32) {
            float4 wv = Wr[i];
            #pragma unroll
            for (int b = 0; b < BB; b++) {
                float4 x4 = xs4[b * 256 + i];
                acc[b] += wv.x * x4.x + wv.y * x4.y + wv.z * x4.z + wv.w * x4.w;
            }
        }
        __syncthreads();
    }
    #pragma unroll
    for (int b = 0; b < BB; b++) {
        #pragma unroll
        for (int o = 16; o; o >>= 1)
            acc[b] += __shfl_xor_sync(0xffffffffu, acc[b], o);
    }
    if (lane == 0) {
        float be = (bias ? bias[e] : 0.f) + (residE ? residE[e] : 0.f);
        #pragma unroll
        for (int b = 0; b < BB; b++) {
            float v = acc[b] + be;
            if (residB) v += residB[(size_t)b * OUT + e];
            if (doRelu) v = fmaxf(v, 0.f);
            out[(size_t)b * OUT + e] = v;
        }
    }
}

// ---------- LayerNorm ----------------------------------------------------------
__global__ void k_ln(const float* __restrict__ in, const float* __restrict__ gamma,
                     const float* __restrict__ beta, float* __restrict__ out) {
    int b = blockIdx.x, t = threadIdx.x;  // 256
    const float* row = in + (size_t)b * DD;
    __shared__ float sred[8];
    __shared__ float smv[2];

    float s = 0.f;
    for (int i = t; i < DD; i += 256) s += row[i];
    #pragma unroll
    for (int o = 16; o; o >>= 1) s += __shfl_xor_sync(0xffffffffu, s, o);
    if ((t & 31) == 0) sred[t >> 5] = s;
    __syncthreads();
    if (t == 0) {
        float m = 0.f;
        #pragma unroll
        for (int i = 0; i < 8; i++) m += sred[i];
        smv[0] = m * (1.f / DD);
    }
    __syncthreads();
    float m = smv[0];

    float v = 0.f;
    for (int i = t; i < DD; i += 256) { float dd2 = row[i] - m; v += dd2 * dd2; }
    #pragma unroll
    for (int o = 16; o; o >>= 1) v += __shfl_xor_sync(0xffffffffu, v, o);
    __syncthreads();
    if ((t & 31) == 0) sred[t >> 5] = v;
    __syncthreads();
    if (t == 0) {
        float vv = 0.f;
        #pragma unroll
        for (int i = 0; i < 8; i++) vv += sred[i];
        smv[1] = rsqrtf(vv * (1.f / DD) + EPSL);
    }
    __syncthreads();
    float r = smv[1];
    for (int i = t; i < DD; i += 256)
        out[(size_t)b * DD + i] = (row[i] - m) * r * gamma[i] + beta[i];
}

extern "C" void kernel_launch(void* const* d_in, const int* in_sizes, int n_in,
                              void* d_out, int out_size) {
    const float* x     = (const float*)d_in[0];
    const float* y     = (const float*)d_in[1];
    const float* cls   = (const float*)d_in[2];
    const float* sep   = (const float*)d_in[3];
    const float* px    = (const float*)d_in[4];
    const float* py    = (const float*)d_in[5];
    const float* Wqkv  = (const float*)d_in[6];
    const float* bqkv  = (const float*)d_in[7];
    const float* Wo    = (const float*)d_in[8];
    const float* bo    = (const float*)d_in[9];
    const float* W1    = (const float*)d_in[10];
    const float* b1    = (const float*)d_in[11];
    const float* W2    = (const float*)d_in[12];
    const float* b2    = (const float*)d_in[13];
    const float* ln1g  = (const float*)d_in[14];
    const float* ln1b  = (const float*)d_in[15];
    const float* ln2g  = (const float*)d_in[16];
    const float* ln2b  = (const float*)d_in[17];
    const int*   x_len = (const int*)d_in[18];
    const int*   y_len = (const int*)d_in[19];
    float* outp = (float*)d_out;

    float *p_oattn, *p_ores, *p_h1, *p_f, *p_f2;
    cudaGetSymbolAddress((void**)&p_oattn, g_oattn);
    cudaGetSymbolAddress((void**)&p_ores,  g_ores);
    cudaGetSymbolAddress((void**)&p_h1,    g_h1);
    cudaGetSymbolAddress((void**)&p_f,     g_f);
    cudaGetSymbolAddress((void**)&p_f2,    g_f2);

    const int SCORES_SMEM = (NH * DD + 2 * DD + 16) * (int)sizeof(float);  // ~74KB
    cudaFuncSetAttribute(k_scores, cudaFuncAttributeMaxDynamicSharedMemorySize, SCORES_SMEM);

    k_q0qhat<<<dim3(NH, 4), 256>>>(Wqkv, bqkv, cls);
    k_scores<<<dim3(16, BB), 256, SCORES_SMEM>>>(x, y, cls, sep, px, py, x_len, y_len);
    k_stats<<<BB * NH, 256>>>(x_len, y_len);
    k_ctx<<<dim3(NC, 8, BB), 128>>>(x, y, cls, sep, px, py, x_len, y_len);
    k_ctxreduce<<<dim3(BB, 4), 512>>>();
    k_gemvV<<<DD / 8, 256>>>(Wqkv, bqkv);
    k_gemv8<<<DD / 8, 256>>>(Wo, p_oattn, bo, cls, nullptr, p_ores, DD, DD, 0,
                             0, nullptr, nullptr, nullptr);
    k_gemv8<<<FF / 8, 256>>>(W1, p_ores, b1, nullptr, nullptr, p_f, DD, FF, 1,
                             1, ln1g, ln1b, p_h1);
    k_gemv8<<<DD / 8, 256>>>(W2, p_f, b2, nullptr, p_h1, p_f2, FF, DD, 0,
                             0, nullptr, nullptr, nullptr);
    k_ln<<<BB, 256>>>(p_f2, ln2g, ln2b, outp);
}

// round 6
// speedup vs baseline: 1.5162x; 1.1055x over previous
#include <cuda_runtime.h>
#include <math.h>

#define DD   1024
#define NH   16
#define HDIM 64
#define FF   2048
#define BB   8
#define SS   1027
#define SP   1056
#define EPSL 1e-5f
#define NC   16             // s-chunks for ctx

__device__ float g_scores[(size_t)BB * NH * SP];     // [b][h][s]
__device__ float g_minv[BB * NH * 2];                // (max, 1/sum)
__device__ float g_qhat[NH * DD];
__device__ float g_qb[NH];
__device__ float g_ctxp[(size_t)BB * NC * NH * DD];  // split-s partial ctx
__device__ float g_ctx[(size_t)BB * NH * DD];
__device__ float g_oattn[BB * DD];
__device__ float g_ores[BB * DD];
__device__ float g_h1[BB * DD];
__device__ float g_f[BB * FF];
__device__ float g_f2[BB * DD];

// ---------- q0 + qhat: grid (NH, 4) ------------------------------------------
__global__ void k_q0qhat(const float* __restrict__ Wqkv, const float* __restrict__ bqkv,
                         const float* __restrict__ cls) {
    int h = blockIdx.x, q = blockIdx.y;
    int t = threadIdx.x;                 // 256
    int w = t >> 5, lane = t & 31;
    __shared__ __align__(16) float clss[DD];
    __shared__ float q0s[HDIM];

    for (int i = t; i < DD / 4; i += 256)
        ((float4*)clss)[i] = ((const float4*)cls)[i];
    __syncthreads();

    const float4* c4 = (const float4*)clss;
    for (int jr = 0; jr < 8; jr++) {
        int j = w * 8 + jr;
        const float4* Wr = (const float4*)(Wqkv + (size_t)(h * HDIM + j) * DD);
        float acc = 0.f;
        for (int i = lane; i < DD / 4; i += 32) {
            float4 wv = Wr[i], cv = c4[i];
            acc += wv.x * cv.x + wv.y * cv.y + wv.z * cv.z + wv.w * cv.w;
        }
        #pragma unroll
        for (int o = 16; o; o >>= 1) acc += __shfl_xor_sync(0xffffffffu, acc, o);
        if (lane == 0) q0s[j] = acc + bqkv[h * HDIM + j];
    }
    __syncthreads();

    int d = q * 256 + t;
    float acc = 0.f;
    #pragma unroll 4
    for (int j = 0; j < HDIM; j++)
        acc += q0s[j] * Wqkv[(size_t)(DD + h * HDIM + j) * DD + d];
    g_qhat[h * DD + d] = acc;
    if (q == 0 && t == 0) {
        float s = 0.f;
        for (int j = 0; j < HDIM; j++) s += q0s[j] * bqkv[DD + h * HDIM + j];
        g_qb[h] = s;
    }
}

// ---------- position fetch helper --------------------------------------------
__device__ __forceinline__ void fetch_pos(
    int s, int lx, int ly, int b, int lane,
    const float* __restrict__ x, const float* __restrict__ y,
    const float* __restrict__ cls, const float* __restrict__ sep,
    const float4* __restrict__ pxs4, const float4* __restrict__ pys4,
    float4 v[8]) {
    if (s == 0) {
        const float4* c4 = (const float4*)cls;
        #pragma unroll
        for (int k = 0; k < 8; k++) v[k] = __ldg(&c4[lane + 32 * k]);
    } else if (s <= lx) {
        const float4* xr = (const float4*)(x + ((size_t)b * 512 + (s - 1)) * DD);
        #pragma unroll
        for (int k = 0; k < 8; k++) {
            float4 a = __ldg(&xr[lane + 32 * k]), p = pxs4[lane + 32 * k];
            v[k].x = a.x + p.x; v[k].y = a.y + p.y; v[k].z = a.z + p.z; v[k].w = a.w + p.w;
        }
    } else if (s == lx + 1 || s == lx + ly + 2) {
        const float4* s4 = (const float4*)sep;
        #pragma unroll
        for (int k = 0; k < 8; k++) v[k] = __ldg(&s4[lane + 32 * k]);
    } else {
        const float4* yr = (const float4*)(y + ((size_t)b * 512 + (s - lx - 2)) * DD);
        #pragma unroll
        for (int k = 0; k < 8; k++) {
            float4 a = __ldg(&yr[lane + 32 * k]), p = pys4[lane + 32 * k];
            v[k].x = a.x + p.x; v[k].y = a.y + p.y; v[k].z = a.z + p.z; v[k].w = a.w + p.w;
        }
    }
}

// ---------- scores: 2 positions per warp, qhat in dynamic smem ---------------
// grid (16, BB), block 256 (8 warps).
__global__ void k_scores(const float* __restrict__ x, const float* __restrict__ y,
                         const float* __restrict__ cls, const float* __restrict__ sep,
                         const float* __restrict__ px, const float* __restrict__ py,
                         const int* __restrict__ x_len, const int* __restrict__ y_len) {
    extern __shared__ __align__(16) float dsm[];
    float* qh  = dsm;                    // 16384
    float* pxs = dsm + NH * DD;          // 1024
    float* pys = pxs + DD;               // 1024
    float* qbs = pys + DD;               // 16
    int b = blockIdx.y;
    int t = threadIdx.x, w = t >> 5, lane = t & 31;

    float4* qh4 = (float4*)qh;
    for (int i = t; i < NH * DD / 4; i += 256) qh4[i] = ((const float4*)g_qhat)[i];
    if (t < 256) { ((float4*)pxs)[t] = ((const float4*)px)[t]; ((float4*)pys)[t] = ((const float4*)py)[t]; }
    if (t < NH) qbs[t] = g_qb[t];
    __syncthreads();

    int lx = x_len[b], ly = y_len[b];
    int Sb = lx + ly + 3;
    const float4* pxs4 = (const float4*)pxs;
    const float4* pys4 = (const float4*)pys;

    for (int s = blockIdx.x * 16 + w * 2; s < Sb; s += 256) {
        bool two = (s + 1 < Sb);
        float4 v0[8], v1[8];
        fetch_pos(s, lx, ly, b, lane, x, y, cls, sep, pxs4, pys4, v0);
        if (two) fetch_pos(s + 1, lx, ly, b, lane, x, y, cls, sep, pxs4, pys4, v1);

        float acc0[NH], acc1[NH];
        #pragma unroll
        for (int h = 0; h < NH; h++) {
            float a0 = 0.f, a1 = 0.f;
            const float4* q4 = qh4 + h * 256;
            #pragma unroll
            for (int k = 0; k < 8; k++) {
                float4 qv = q4[lane + 32 * k];
                a0 += qv.x * v0[k].x + qv.y * v0[k].y + qv.z * v0[k].z + qv.w * v0[k].w;
                if (two)
                    a1 += qv.x * v1[k].x + qv.y * v1[k].y + qv.z * v1[k].z + qv.w * v1[k].w;
            }
            acc0[h] = a0; acc1[h] = a1;
        }
        #pragma unroll
        for (int h = 0; h < NH; h++) {
            #pragma unroll
            for (int o = 16; o; o >>= 1) {
                acc0[h] += __shfl_xor_sync(0xffffffffu, acc0[h], o);
                acc1[h] += __shfl_xor_sync(0xffffffffu, acc1[h], o);
            }
        }
        if (lane == 0) {
            #pragma unroll
            for (int h = 0; h < NH; h++) {
                float* sp = g_scores + ((size_t)b * NH + h) * SP + s;
                sp[0] = (acc0[h] + qbs[h]) * 0.125f;
                if (two) sp[1] = (acc1[h] + qbs[h]) * 0.125f;
            }
        }
    }
}

// ---------- softmax stats ----------------------------------------------------
__global__ void k_stats(const int* __restrict__ x_len, const int* __restrict__ y_len) {
    int bh = blockIdx.x;
    int b  = bh >> 4;
    int Sb = x_len[b] + y_len[b] + 3;
    int t  = threadIdx.x;                // 256
    const float* sc = g_scores + (size_t)bh * SP;
    __shared__ float sred[8];

    float m = -1e30f;
    for (int s = t; s < Sb; s += 256) m = fmaxf(m, sc[s]);
    #pragma unroll
    for (int o = 16; o; o >>= 1) m = fmaxf(m, __shfl_xor_sync(0xffffffffu, m, o));
    if ((t & 31) == 0) sred[t >> 5] = m;
    __syncthreads();
    m = sred[0];
    #pragma unroll
    for (int i = 1; i < 8; i++) m = fmaxf(m, sred[i]);

    float sum = 0.f;
    for (int s = t; s < Sb; s += 256) sum += __expf(sc[s] - m);
    #pragma unroll
    for (int o = 16; o; o >>= 1) sum += __shfl_xor_sync(0xffffffffu, sum, o);
    __syncthreads();
    if ((t & 31) == 0) sred[t >> 5] = sum;
    __syncthreads();
    if (t == 0) {
        float ss = 0.f;
        #pragma unroll
        for (int i = 0; i < 8; i++) ss += sred[i];
        g_minv[bh * 2]     = m;
        g_minv[bh * 2 + 1] = 1.f / ss;
    }
}

// ---------- ctx partials: grid (NC, 8, BB), block 128 -------------------------
__global__ void k_ctx(const float* __restrict__ x, const float* __restrict__ y,
                      const float* __restrict__ cls, const float* __restrict__ sep,
                      const float* __restrict__ px, const float* __restrict__ py,
                      const int* __restrict__ x_len, const int* __restrict__ y_len) {
    int c  = blockIdx.x;
    int dq = blockIdx.y;
    int b  = blockIdx.z;
    int t  = threadIdx.x;          // 128
    int d  = dq * 128 + t;
    int lx = x_len[b], ly = y_len[b];
    int Sb = lx + ly + 3;
    int cl = (Sb + NC - 1) / NC;
    int s0 = c * cl, s1 = min(s0 + cl, Sb);
    int n  = s1 - s0;

    float* outp = g_ctxp + (((size_t)b * NC + c) * NH) * DD + d;
    if (n <= 0) {
        #pragma unroll
        for (int h = 0; h < NH; h++) outp[(size_t)h * DD] = 0.f;
        return;
    }

    __shared__ float a[NH][68];    // cl <= ceil(1027/16) = 65
    __shared__ float minv[NH * 2];
    if (t < NH * 2) minv[t] = g_minv[b * NH * 2 + t];
    __syncthreads();
    for (int i = t; i < n * NH; i += 128) {
        int h = i & 15, ss = i >> 4;
        a[h][ss] = __expf(g_scores[((size_t)b * NH + h) * SP + s0 + ss] - minv[h * 2]) * minv[h * 2 + 1];
    }
    __syncthreads();

    float acc[NH];
    #pragma unroll
    for (int h = 0; h < NH; h++) acc[h] = 0.f;

    if (s0 == 0) {
        float v = cls[d];
        #pragma unroll
        for (int h = 0; h < NH; h++) acc[h] += a[h][0] * v;
    }
    {
        int p0 = max(s0, 1), p1 = min(s1, lx + 1);
        float pxd = px[d];
        const float* xp = x + (size_t)b * 512 * DD + d;
        #pragma unroll 4
        for (int s = p0; s < p1; s++) {
            float v = xp[(size_t)(s - 1) * DD] + pxd;
            int ss = s - s0;
            #pragma unroll
            for (int h = 0; h < NH; h++) acc[h] += a[h][ss] * v;
        }
    }
    {
        float sd = sep[d];
        int sA = lx + 1, sB = lx + ly + 2;
        if (sA >= s0 && sA < s1) {
            #pragma unroll
            for (int h = 0; h < NH; h++) acc[h] += a[h][sA - s0] * sd;
        }
        if (sB >= s0 && sB < s1) {
            #pragma unroll
            for (int h = 0; h < NH; h++) acc[h] += a[h][sB - s0] * sd;
        }
    }
    {
        int p0 = max(s0, lx + 2), p1 = min(s1, lx + ly + 2);
        float pyd = py[d];
        const float* yp = y + (size_t)b * 512 * DD + d;
        #pragma unroll 4
        for (int s = p0; s < p1; s++) {
            float v = yp[(size_t)(s - lx - 2) * DD] + pyd;
            int ss = s - s0;
            #pragma unroll
            for (int h = 0; h < NH; h++) acc[h] += a[h][ss] * v;
        }
    }
    #pragma unroll
    for (int h = 0; h < NH; h++) outp[(size_t)h * DD] = acc[h];
}

// ---------- reduce ctx chunks: grid (BB, 32), block 512 ------------------------
__global__ void k_ctxreduce() {
    int b = blockIdx.x;
    int q = blockIdx.y;            // 0..31
    int t = threadIdx.x;           // 512
    int idx = q * 512 + t;         // over NH*DD = 16384
    float s = 0.f;
    #pragma unroll
    for (int c = 0; c < NC; c++)
        s += g_ctxp[((size_t)b * NC + c) * (NH * DD) + idx];
    g_ctx[(size_t)b * (NH * DD) + idx] = s;
}

// ---------- V projection: 1 row/warp, per-head ctx -----------------------------
__global__ void k_gemvV(const float* __restrict__ Wqkv, const float* __restrict__ bqkv) {
    __shared__ __align__(16) float xs[BB * DD];
    int t = threadIdx.x;           // 256
    int w = t >> 5, lane = t & 31;
    int e = blockIdx.x * 8 + w;
    int h = (blockIdx.x * 8) >> 6;

    float4* xs4 = (float4*)xs;
    for (int i = t; i < BB * DD / 4; i += 256) {
        int b = i >> 8, j4 = i & 255;
        xs4[i] = ((const float4*)(g_ctx + ((size_t)b * NH + h) * DD))[j4];
    }
    __syncthreads();

    const float4* Wr = (const float4*)(Wqkv + (size_t)(2 * DD + e) * DD);
    float acc[BB];
    #pragma unroll
    for (int b = 0; b < BB; b++) acc[b] = 0.f;
    for (int i = lane; i < DD / 4; i += 32) {
        float4 wv = Wr[i];
        #pragma unroll
        for (int b = 0; b < BB; b++) {
            float4 x4 = xs4[b * 256 + i];
            acc[b] += wv.x * x4.x + wv.y * x4.y + wv.z * x4.z + wv.w * x4.w;
        }
    }
    #pragma unroll
    for (int b = 0; b < BB; b++) {
        #pragma unroll
        for (int o = 16; o; o >>= 1)
            acc[b] += __shfl_xor_sync(0xffffffffu, acc[b], o);
    }
    if (lane == 0) {
        float be = bqkv[2 * DD + e];
        #pragma unroll
        for (int b = 0; b < BB; b++)
            g_oattn[(size_t)b * DD + e] = acc[b] + be;
    }
}

// ---------- batch-shared GEMV, optional fused input-LN --------------------------
__global__ void k_gemv8(const float* __restrict__ W, const float* __restrict__ xin,
                        const float* __restrict__ bias, const float* __restrict__ residE,
                        const float* __restrict__ residB, float* __restrict__ out,
                        int IN, int OUT, int doRelu,
                        int doLN, const float* __restrict__ lng, const float* __restrict__ lnb,
                        float* __restrict__ h1out) {
    __shared__ __align__(16) float xs[BB * 1024];
    __shared__ __align__(16) float gs[1024], bs[1024];
    int t = threadIdx.x;           // 256
    int w = t >> 5, lane = t & 31;
    int e = blockIdx.x * 8 + w;

    float acc[BB];
    #pragma unroll
    for (int b = 0; b < BB; b++) acc[b] = 0.f;

    float4* xs4 = (float4*)xs;
    int nchunk = IN >> 10;
    for (int kc = 0; kc < nchunk; kc++) {
        for (int i = t; i < BB * 256; i += 256) {
            int b = i >> 8, j4 = i & 255;
            xs4[i] = ((const float4*)(xin + (size_t)b * IN + kc * 1024))[j4];
        }
        if (doLN) {
            if (t < 256) { ((float4*)gs)[t] = ((const float4*)lng)[t]; ((float4*)bs)[t] = ((const float4*)lnb)[t]; }
            __syncthreads();
            float* row = xs + w * 1024;
            float s = 0.f;
            #pragma unroll
            for (int j = 0; j < 32; j++) s += row[lane + 32 * j];
            #pragma unroll
            for (int o = 16; o; o >>= 1) s += __shfl_xor_sync(0xffffffffu, s, o);
            float m = s * (1.f / 1024.f);
            float v = 0.f;
            #pragma unroll
            for (int j = 0; j < 32; j++) { float dd2 = row[lane + 32 * j] - m; v += dd2 * dd2; }
            #pragma unroll
            for (int o = 16; o; o >>= 1) v += __shfl_xor_sync(0xffffffffu, v, o);
            float r = rsqrtf(v * (1.f / 1024.f) + EPSL);
            #pragma unroll
            for (int j = 0; j < 32; j++) {
                int idx = lane + 32 * j;
                row[idx] = (row[idx] - m) * r * gs[idx] + bs[idx];
            }
            __syncthreads();
            if (h1out && blockIdx.x == 0) {
                for (int i = t; i < BB * 256; i += 256)
                    ((float4*)h1out)[i] = xs4[i];
            }
        } else {
            __syncthreads();
        }
        const float4* Wr = (const float4*)(W + (size_t)e * IN + kc * 1024);
        for (int i = lane; i < 256; i += 32) {
            float4 wv = Wr[i];
            #pragma unroll
            for (int b = 0; b < BB; b++) {
                float4 x4 = xs4[b * 256 + i];
                acc[b] += wv.x * x4.x + wv.y * x4.y + wv.z * x4.z + wv.w * x4.w;
            }
        }
        __syncthreads();
    }
    #pragma unroll
    for (int b = 0; b < BB; b++) {
        #pragma unroll
        for (int o = 16; o; o >>= 1)
            acc[b] += __shfl_xor_sync(0xffffffffu, acc[b], o);
    }
    if (lane == 0) {
        float be = (bias ? bias[e] : 0.f) + (residE ? residE[e] : 0.f);
        #pragma unroll
        for (int b = 0; b < BB; b++) {
            float v = acc[b] + be;
            if (residB) v += residB[(size_t)b * OUT + e];
            if (doRelu) v = fmaxf(v, 0.f);
            out[(size_t)b * OUT + e] = v;
        }
    }
}

// ---------- LayerNorm ------------------------------------------------------------
__global__ void k_ln(const float* __restrict__ in, const float* __restrict__ gamma,
                     const float* __restrict__ beta, float* __restrict__ out) {
    int b = blockIdx.x, t = threadIdx.x;  // 256
    const float* row = in + (size_t)b * DD;
    __shared__ float sred[8];
    __shared__ float smv[2];

    float s = 0.f;
    for (int i = t; i < DD; i += 256) s += row[i];
    #pragma unroll
    for (int o = 16; o; o >>= 1) s += __shfl_xor_sync(0xffffffffu, s, o);
    if ((t & 31) == 0) sred[t >> 5] = s;
    __syncthreads();
    if (t == 0) {
        float m = 0.f;
        #pragma unroll
        for (int i = 0; i < 8; i++) m += sred[i];
        smv[0] = m * (1.f / DD);
    }
    __syncthreads();
    float m = smv[0];

    float v = 0.f;
    for (int i = t; i < DD; i += 256) { float dd2 = row[i] - m; v += dd2 * dd2; }
    #pragma unroll
    for (int o = 16; o; o >>= 1) v += __shfl_xor_sync(0xffffffffu, v, o);
    __syncthreads();
    if ((t & 31) == 0) sred[t >> 5] = v;
    __syncthreads();
    if (t == 0) {
        float vv = 0.f;
        #pragma unroll
        for (int i = 0; i < 8; i++) vv += sred[i];
        smv[1] = rsqrtf(vv * (1.f / DD) + EPSL);
    }
    __syncthreads();
    float r = smv[1];
    for (int i = t; i < DD; i += 256)
        out[(size_t)b * DD + i] = (row[i] - m) * r * gamma[i] + beta[i];
}

extern "C" void kernel_launch(void* const* d_in, const int* in_sizes, int n_in,
                              void* d_out, int out_size) {
    const float* x     = (const float*)d_in[0];
    const float* y     = (const float*)d_in[1];
    const float* cls   = (const float*)d_in[2];
    const float* sep   = (const float*)d_in[3];
    const float* px    = (const float*)d_in[4];
    const float* py    = (const float*)d_in[5];
    const float* Wqkv  = (const float*)d_in[6];
    const float* bqkv  = (const float*)d_in[7];
    const float* Wo    = (const float*)d_in[8];
    const float* bo    = (const float*)d_in[9];
    const float* W1    = (const float*)d_in[10];
    const float* b1    = (const float*)d_in[11];
    const float* W2    = (const float*)d_in[12];
    const float* b2    = (const float*)d_in[13];
    const float* ln1g  = (const float*)d_in[14];
    const float* ln1b  = (const float*)d_in[15];
    const float* ln2g  = (const float*)d_in[16];
    const float* ln2b  = (const float*)d_in[17];
    const int*   x_len = (const int*)d_in[18];
    const int*   y_len = (const int*)d_in[19];
    float* outp = (float*)d_out;

    float *p_oattn, *p_ores, *p_h1, *p_f, *p_f2;
    cudaGetSymbolAddress((void**)&p_oattn, g_oattn);
    cudaGetSymbolAddress((void**)&p_ores,  g_ores);
    cudaGetSymbolAddress((void**)&p_h1,    g_h1);
    cudaGetSymbolAddress((void**)&p_f,     g_f);
    cudaGetSymbolAddress((void**)&p_f2,    g_f2);

    const int SCORES_SMEM = (NH * DD + 2 * DD + 16) * (int)sizeof(float);  // ~74KB
    cudaFuncSetAttribute(k_scores, cudaFuncAttributeMaxDynamicSharedMemorySize, SCORES_SMEM);

    k_q0qhat<<<dim3(NH, 4), 256>>>(Wqkv, bqkv, cls);
    k_scores<<<dim3(16, BB), 256, SCORES_SMEM>>>(x, y, cls, sep, px, py, x_len, y_len);
    k_stats<<<BB * NH, 256>>>(x_len, y_len);
    k_ctx<<<dim3(NC, 8, BB), 128>>>(x, y, cls, sep, px, py, x_len, y_len);
    k_ctxreduce<<<dim3(BB, 32), 512>>>();
    k_gemvV<<<DD / 8, 256>>>(Wqkv, bqkv);
    k_gemv8<<<DD / 8, 256>>>(Wo, p_oattn, bo, cls, nullptr, p_ores, DD, DD, 0,
                             0, nullptr, nullptr, nullptr);
    k_gemv8<<<FF / 8, 256>>>(W1, p_ores, b1, nullptr, nullptr, p_f, DD, FF, 1,
                             1, ln1g, ln1b, p_h1);
    k_gemv8<<<DD / 8, 256>>>(W2, p_f, b2, nullptr, p_h1, p_f2, FF, DD, 0,
                             0, nullptr, nullptr, nullptr);
    k_ln<<<BB, 256>>>(p_f2, ln2g, ln2b, outp);
}